// round 5
// baseline (speedup 1.0000x reference)
#include <cuda_runtime.h>
#include <cuda_fp16.h>
#include <cstdint>

// GCN layer: out = relu(D^-1/2 (I ∪ A) D^-1/2 (x @ W^T))
// N=8192, E=262144 (set semantics -> dedupe), D_IN=D_OUT=256.

#define NN    8192
#define DD    256
#define WPR   (NN / 32)
#define MAXD  128

__device__ uint32_t g_bits[NN * WPR];     // 8 MB dedup bitmap
__device__ int      g_deg[NN];
__device__ int      g_nbr[NN * MAXD];     // neighbor lists
__device__ __half   g_hh[NN * DD];        // 4 MB scaled h in fp16
__device__ int      g_is64;

// ---------------------------------------------------------------- init ----
__global__ void k_init(int n, const int* __restrict__ ei32) {
    int idx = blockIdx.x * blockDim.x + threadIdx.x;
    if (idx < n * WPR) {
        int row = idx >> 8;
        int w   = idx & (WPR - 1);
        g_bits[idx] = (w == (row >> 5)) ? (1u << (row & 31)) : 0u;
    }
    if (idx < n) {
        g_deg[idx] = 1;
        g_nbr[idx * MAXD] = idx;
    }
    if (blockIdx.x == 0) {   // dtype sniff: int64 LE => odd int32 words zero
        __shared__ int zc;
        if (threadIdx.x == 0) zc = 0;
        __syncthreads();
        int z = 0;
        for (int t = threadIdx.x; t < 1024; t += 256)
            z += (ei32[2 * t + 1] == 0);
        atomicAdd(&zc, z);
        __syncthreads();
        if (threadIdx.x == 0) g_is64 = (zc >= 1000) ? 1 : 0;
    }
}

// --------------------------------------------------------------- edges ----
__global__ void k_edges(const int* __restrict__ ei32, int E) {
    int e = blockIdx.x * blockDim.x + threadIdx.x;
    if (e < E) {
        int r, c;
        if (g_is64) { r = ei32[2 * e];  c = ei32[2 * (E + e)]; }
        else        { r = ei32[e];      c = ei32[E + e]; }
        r &= (NN - 1);
        c &= (NN - 1);
        uint32_t bit = 1u << (c & 31);
        uint32_t old = atomicOr(&g_bits[r * WPR + (c >> 5)], bit);
        if (!(old & bit)) {
            int p = atomicAdd(&g_deg[r], 1);
            if (p < MAXD) g_nbr[r * MAXD + p] = c;
        }
    }
}

// ---------------------------------------------------------------- gemm ----
// 128x128 tile, BK=32, 256 threads, 8x8/thread, FFMA2 with pre-duplicated A.
#define BM 128
#define BN 128
#define BK 32

__device__ __forceinline__ void ffma2(unsigned long long& acc,
                                      unsigned long long a,
                                      unsigned long long b) {
    asm("fma.rn.f32x2 %0, %1, %2, %0;" : "+l"(acc) : "l"(a), "l"(b));
}
__device__ __forceinline__ float2 unpack2(unsigned long long v) {
    float2 f;
    asm("mov.b64 {%0, %1}, %2;" : "=f"(f.x), "=f"(f.y) : "l"(v));
    return f;
}

__global__ __launch_bounds__(256, 1) void k_gemm(const float* __restrict__ x,
                                                 const float* __restrict__ W) {
    __shared__ float2 Xs2[BM][BK + 2];   // [m][k] dup pairs, 272B row stride
    __shared__ float  Ws[BK][BN + 4];    // [k][n]

    int tid = threadIdx.x;
    int m0  = blockIdx.x * BM;
    int n0  = blockIdx.y * BN;
    int tx  = tid & 15;                  // N (8 cols)
    int ty  = tid >> 4;                  // M (8 rows)

    unsigned long long acc[8][4];
#pragma unroll
    for (int i = 0; i < 8; i++)
#pragma unroll
        for (int p = 0; p < 4; p++) acc[i][p] = 0ull;

    float4 xr[4], wr[4];
#pragma unroll
    for (int i = 0; i < 4; i++) {
        int f = tid + i * 256, r = f >> 3, q = f & 7;
        xr[i] = *(const float4*)&x[(m0 + r) * DD + q * 4];
        wr[i] = *(const float4*)&W[(n0 + r) * DD + q * 4];
    }

    for (int kt = 0; kt < DD / BK; kt++) {
        __syncthreads();
#pragma unroll
        for (int i = 0; i < 4; i++) {
            int f = tid + i * 256, r = f >> 3, q = f & 7;
            Xs2[r][q * 4 + 0] = make_float2(xr[i].x, xr[i].x);
            Xs2[r][q * 4 + 1] = make_float2(xr[i].y, xr[i].y);
            Xs2[r][q * 4 + 2] = make_float2(xr[i].z, xr[i].z);
            Xs2[r][q * 4 + 3] = make_float2(xr[i].w, xr[i].w);
            Ws[q * 4 + 0][r] = wr[i].x; Ws[q * 4 + 1][r] = wr[i].y;
            Ws[q * 4 + 2][r] = wr[i].z; Ws[q * 4 + 3][r] = wr[i].w;
        }
        __syncthreads();

        if (kt < DD / BK - 1) {
            int k0 = (kt + 1) * BK;
#pragma unroll
            for (int i = 0; i < 4; i++) {
                int f = tid + i * 256, r = f >> 3, q = f & 7;
                xr[i] = *(const float4*)&x[(m0 + r) * DD + k0 + q * 4];
                wr[i] = *(const float4*)&W[(n0 + r) * DD + k0 + q * 4];
            }
        }

#pragma unroll
        for (int k = 0; k < BK; k++) {
            ulonglong2 b0 = *(const ulonglong2*)&Ws[k][tx * 8];
            ulonglong2 b1 = *(const ulonglong2*)&Ws[k][tx * 8 + 4];
            unsigned long long ap[8];
#pragma unroll
            for (int i = 0; i < 8; i++)
                ap[i] = *(const unsigned long long*)&Xs2[ty * 8 + i][k];
#pragma unroll
            for (int i = 0; i < 8; i++) {
                ffma2(acc[i][0], ap[i], b0.x);
                ffma2(acc[i][1], ap[i], b0.y);
                ffma2(acc[i][2], ap[i], b1.x);
                ffma2(acc[i][3], ap[i], b1.y);
            }
        }
    }

#pragma unroll
    for (int i = 0; i < 8; i++) {
        int m = m0 + ty * 8 + i;
        float dm = rsqrtf((float)g_deg[m] + 1e-5f);
        float2 p0 = unpack2(acc[i][0]), p1 = unpack2(acc[i][1]);
        float2 p2 = unpack2(acc[i][2]), p3 = unpack2(acc[i][3]);
        __half2 h0 = __float22half2_rn(make_float2(p0.x * dm, p0.y * dm));
        __half2 h1 = __float22half2_rn(make_float2(p1.x * dm, p1.y * dm));
        __half2 h2 = __float22half2_rn(make_float2(p2.x * dm, p2.y * dm));
        __half2 h3 = __float22half2_rn(make_float2(p3.x * dm, p3.y * dm));
        uint4 v;
        v.x = *(uint32_t*)&h0; v.y = *(uint32_t*)&h1;
        v.z = *(uint32_t*)&h2; v.w = *(uint32_t*)&h3;
        *(uint4*)&g_hh[m * DD + n0 + tx * 8] = v;
    }
}

// ---------------------------------------------------------------- spmm ----
// one warp per row; lane owns 8 columns; 8-neighbor fp16 tree reduce.
__device__ __forceinline__ uint4 hadd4(uint4 a, uint4 b) {
    uint4 r;
    *(__half2*)&r.x = __hadd2(*(__half2*)&a.x, *(__half2*)&b.x);
    *(__half2*)&r.y = __hadd2(*(__half2*)&a.y, *(__half2*)&b.y);
    *(__half2*)&r.z = __hadd2(*(__half2*)&a.z, *(__half2*)&b.z);
    *(__half2*)&r.w = __hadd2(*(__half2*)&a.w, *(__half2*)&b.w);
    return r;
}
__device__ __forceinline__ void acc_u4(float* a, uint4 v) {
    float2 f0 = __half22float2(*(__half2*)&v.x);
    float2 f1 = __half22float2(*(__half2*)&v.y);
    float2 f2 = __half22float2(*(__half2*)&v.z);
    float2 f3 = __half22float2(*(__half2*)&v.w);
    a[0] += f0.x; a[1] += f0.y; a[2] += f1.x; a[3] += f1.y;
    a[4] += f2.x; a[5] += f2.y; a[6] += f3.x; a[7] += f3.y;
}

__global__ __launch_bounds__(256) void k_spmm(float* __restrict__ out) {
    __shared__ int s_nbr[8][MAXD];
    int lane = threadIdx.x & 31;
    int w    = threadIdx.x >> 5;
    int i    = blockIdx.x * 8 + w;

    int dg = min(g_deg[i], MAXD);
    for (int t = lane; t < dg; t += 32) s_nbr[w][t] = g_nbr[i * MAXD + t];
    __syncwarp();

    const uint4* __restrict__ h4 = (const uint4*)g_hh;  // 32 uint4 per row
    float acc[8] = {0.f, 0.f, 0.f, 0.f, 0.f, 0.f, 0.f, 0.f};

    int t = 0;
    for (; t + 8 <= dg; t += 8) {
        int4 ja = *(const int4*)&s_nbr[w][t];
        int4 jb = *(const int4*)&s_nbr[w][t + 4];
        uint4 v0 = h4[ja.x * 32 + lane];
        uint4 v1 = h4[ja.y * 32 + lane];
        uint4 v2 = h4[ja.z * 32 + lane];
        uint4 v3 = h4[ja.w * 32 + lane];
        uint4 v4 = h4[jb.x * 32 + lane];
        uint4 v5 = h4[jb.y * 32 + lane];
        uint4 v6 = h4[jb.z * 32 + lane];
        uint4 v7 = h4[jb.w * 32 + lane];
        uint4 s = hadd4(hadd4(hadd4(v0, v1), hadd4(v2, v3)),
                        hadd4(hadd4(v4, v5), hadd4(v6, v7)));
        acc_u4(acc, s);
    }
    for (; t + 2 <= dg; t += 2) {
        uint4 va = h4[s_nbr[w][t] * 32 + lane];
        uint4 vb = h4[s_nbr[w][t + 1] * 32 + lane];
        acc_u4(acc, hadd4(va, vb));
    }
    for (; t < dg; t++)
        acc_u4(acc, h4[s_nbr[w][t] * 32 + lane]);

    float di = rsqrtf((float)g_deg[i] + 1e-5f);
    float4 r0 = make_float4(fmaxf(acc[0] * di, 0.f), fmaxf(acc[1] * di, 0.f),
                            fmaxf(acc[2] * di, 0.f), fmaxf(acc[3] * di, 0.f));
    float4 r1 = make_float4(fmaxf(acc[4] * di, 0.f), fmaxf(acc[5] * di, 0.f),
                            fmaxf(acc[6] * di, 0.f), fmaxf(acc[7] * di, 0.f));
    *(float4*)&out[i * DD + lane * 8]     = r0;
    *(float4*)&out[i * DD + lane * 8 + 4] = r1;
}

// -------------------------------------------------------------- launch ----
extern "C" void kernel_launch(void* const* d_in, const int* in_sizes, int n_in,
                              void* d_out, int out_size) {
    const float* x    = (const float*)d_in[0];
    const int*   ei32 = (const int*)d_in[1];
    const float* W    = (const float*)d_in[2];
    float*       out  = (float*)d_out;

    int n = in_sizes[0] / DD;   // 8192
    int E = in_sizes[1] / 2;    // 262144

    k_init<<<(n * WPR + 255) / 256, 256>>>(n, ei32);
    k_edges<<<(E + 255) / 256, 256>>>(ei32, E);

    dim3 gg(n / BM, DD / BN);
    k_gemm<<<gg, 256>>>(x, W);

    k_spmm<<<n / 8, 256>>>(out);
}

// round 7
// speedup vs baseline: 1.1849x; 1.1849x over previous
#include <cuda_runtime.h>
#include <cuda_fp16.h>
#include <cuda_bf16.h>
#include <cstdint>

// GCN layer: out = relu(D^-1/2 (I ∪ A) D^-1/2 (x @ W^T))
// N=8192, E=262144 (set semantics -> dedupe), D_IN=D_OUT=256.
//
//   k_init  : bitmap diag, deg=1, nbr seed; block0 sniffs int64/int32
//   k_edges : atomicOr dedup -> per-row neighbor lists
//   k_gemm  : mma.sync bf16 HMMA, hi/lo split (fp32-class), h scaled -> fp16
//   k_spmm  : out[i][:] = relu(dinv[i] * sum_j g_hh[j][:])

#define NN    8192
#define DD    256
#define WPR   (NN / 32)
#define MAXD  128

__device__ uint32_t g_bits[NN * WPR];
__device__ int      g_deg[NN];
__device__ int      g_nbr[NN * MAXD];
__device__ __half   g_hh[NN * DD];        // 4 MB scaled h in fp16
__device__ int      g_is64;

// ---------------------------------------------------------------- init ----
__global__ void k_init(int n, const int* __restrict__ ei32) {
    int idx = blockIdx.x * blockDim.x + threadIdx.x;
    if (idx < n * WPR) {
        int row = idx >> 8;
        int w   = idx & (WPR - 1);
        g_bits[idx] = (w == (row >> 5)) ? (1u << (row & 31)) : 0u;
    }
    if (idx < n) {
        g_deg[idx] = 1;
        g_nbr[idx * MAXD] = idx;
    }
    if (blockIdx.x == 0) {   // int64 LE => odd int32 words zero
        __shared__ int zc;
        if (threadIdx.x == 0) zc = 0;
        __syncthreads();
        int z = 0;
        for (int t = threadIdx.x; t < 1024; t += 256)
            z += (ei32[2 * t + 1] == 0);
        atomicAdd(&zc, z);
        __syncthreads();
        if (threadIdx.x == 0) g_is64 = (zc >= 1000) ? 1 : 0;
    }
}

// --------------------------------------------------------------- edges ----
__global__ void k_edges(const int* __restrict__ ei32, int E) {
    int e = blockIdx.x * blockDim.x + threadIdx.x;
    if (e < E) {
        int r, c;
        if (g_is64) { r = ei32[2 * e];  c = ei32[2 * (E + e)]; }
        else        { r = ei32[e];      c = ei32[E + e]; }
        r &= (NN - 1);
        c &= (NN - 1);
        uint32_t bit = 1u << (c & 31);
        uint32_t old = atomicOr(&g_bits[r * WPR + (c >> 5)], bit);
        if (!(old & bit)) {
            int p = atomicAdd(&g_deg[r], 1);
            if (p < MAXD) g_nbr[r * MAXD + p] = c;
        }
    }
}

// ---------------------------------------------------------------- gemm ----
// h = x @ W^T via mma.sync m16n8k16 bf16, hi/lo split (3 terms, K=768).
// CTA tile 128x128, 8 warps (warp tile 32x64), 12 K-chunks of 64.
#define LDSS 72   // smem row stride in bf16 elements (144B, conflict-free)

__device__ __forceinline__ uint32_t smem_u32(const void* p) {
    uint32_t a;
    asm("{ .reg .u64 t; cvta.to.shared.u64 t, %1; cvt.u32.u64 %0, t; }"
        : "=r"(a) : "l"(p));
    return a;
}
__device__ __forceinline__ uint32_t cvt_hi2(float a, float b) {
    __nv_bfloat162 h = __floats2bfloat162_rn(a, b);
    return *(uint32_t*)&h;
}
__device__ __forceinline__ uint32_t cvt_lo2(float a, float b) {
    __nv_bfloat162 h = __floats2bfloat162_rn(a, b);
    float2 hf = __bfloat1622float2(h);
    __nv_bfloat162 l = __floats2bfloat162_rn(a - hf.x, b - hf.y);
    return *(uint32_t*)&l;
}
__device__ __forceinline__ uint4 cvt8(float4 f0, float4 f1, int lo) {
    uint4 v;
    if (lo) {
        v.x = cvt_lo2(f0.x, f0.y); v.y = cvt_lo2(f0.z, f0.w);
        v.z = cvt_lo2(f1.x, f1.y); v.w = cvt_lo2(f1.z, f1.w);
    } else {
        v.x = cvt_hi2(f0.x, f0.y); v.y = cvt_hi2(f0.z, f0.w);
        v.z = cvt_hi2(f1.x, f1.y); v.w = cvt_hi2(f1.z, f1.w);
    }
    return v;
}
#define LDMX4(r0, r1, r2, r3, a)                                             \
    asm volatile("ldmatrix.sync.aligned.m8n8.x4.shared.b16 {%0,%1,%2,%3}, [%4];" \
                 : "=r"(r0), "=r"(r1), "=r"(r2), "=r"(r3) : "r"(a))
#define MMA(c, a0, a1, a2, a3, b0, b1)                                       \
    asm volatile("mma.sync.aligned.m16n8k16.row.col.f32.bf16.bf16.f32 "      \
                 "{%0,%1,%2,%3}, {%4,%5,%6,%7}, {%8,%9}, {%0,%1,%2,%3};"     \
                 : "+f"((c)[0]), "+f"((c)[1]), "+f"((c)[2]), "+f"((c)[3])    \
                 : "r"(a0), "r"(a1), "r"(a2), "r"(a3), "r"(b0), "r"(b1))

__global__ __launch_bounds__(256, 1) void k_gemm(const float* __restrict__ x,
                                                 const float* __restrict__ W) {
    __shared__ __nv_bfloat16 As[128 * LDSS];
    __shared__ __nv_bfloat16 Bs[128 * LDSS];

    int tid  = threadIdx.x;
    int lane = tid & 31;
    int wid  = tid >> 5;
    int wm   = (wid >> 1) * 32;           // warp row offset (4 warps on M)
    int wn   = (wid & 1) * 64;            // warp col offset (2 warps on N)
    int m0   = blockIdx.x * 128;
    int n0   = blockIdx.y * 128;

    uint32_t asb = smem_u32(As);
    uint32_t bsb = smem_u32(Bs);

    // ldmatrix lane address components: row = base + (lane&15), col = (lane>>4)*8
    int lrow = lane & 15;
    int lcol = (lane >> 4) * 8;

    float acc[2][8][4];
#pragma unroll
    for (int i = 0; i < 2; i++)
#pragma unroll
        for (int j = 0; j < 8; j++)
#pragma unroll
            for (int q = 0; q < 4; q++) acc[i][j][q] = 0.f;

    int c_row = tid >> 3;                 // conversion: 128 rows, 2 waves
    int c_grp = tid & 7;                  // 8 groups of 8 floats per row

    for (int c = 0; c < 12; c++) {
        int term = c >> 2;                // 0: xh*Wh  1: xl*Wh  2: xh*Wl
        int k0   = (c & 3) * 64;
        int a_lo = (term == 1);
        int b_lo = (term == 2);

        __syncthreads();                  // WAR: prev chunk's reads done
#pragma unroll
        for (int i = 0; i < 4; i++) {
            int row = c_row + (i >> 1) * 32 + (i & 1) * 64;  // covers 0..127
            const float4* sa = (const float4*)&x[(m0 + row) * DD + k0 + c_grp * 8];
            const float4* sb = (const float4*)&W[(n0 + row) * DD + k0 + c_grp * 8];
            *(uint4*)&As[row * LDSS + c_grp * 8] = cvt8(sa[0], sa[1], a_lo);
            *(uint4*)&Bs[row * LDSS + c_grp * 8] = cvt8(sb[0], sb[1], b_lo);
        }
        __syncthreads();

#pragma unroll
        for (int kk = 0; kk < 4; kk++) {
            int kc = kk * 16 + lcol;
            uint32_t a[2][4], b[4][4];
#pragma unroll
            for (int mi = 0; mi < 2; mi++) {
                uint32_t ad = asb + ((wm + mi * 16 + lrow) * LDSS + kc) * 2;
                LDMX4(a[mi][0], a[mi][1], a[mi][2], a[mi][3], ad);
            }
#pragma unroll
            for (int nj = 0; nj < 4; nj++) {
                uint32_t bd = bsb + ((wn + nj * 16 + lrow) * LDSS + kc) * 2;
                LDMX4(b[nj][0], b[nj][1], b[nj][2], b[nj][3], bd);
            }
#pragma unroll
            for (int mi = 0; mi < 2; mi++)
#pragma unroll
                for (int nf = 0; nf < 8; nf++) {
                    int nj = nf >> 1, hi = nf & 1;
                    MMA(acc[mi][nf], a[mi][0], a[mi][1], a[mi][2], a[mi][3],
                        b[nj][hi], b[nj][2 + hi]);
                }
        }
    }

    // epilogue: scale rows by rsqrt(deg+eps), store fp16
    int g = lane >> 2;                    // 0..7 row-in-frag
    int q = lane & 3;                     // col pair
#pragma unroll
    for (int mi = 0; mi < 2; mi++) {
        int r0 = m0 + wm + mi * 16 + g;
        int r1 = r0 + 8;
        float d0 = rsqrtf((float)g_deg[r0] + 1e-5f);
        float d1 = rsqrtf((float)g_deg[r1] + 1e-5f);
#pragma unroll
        for (int nf = 0; nf < 8; nf++) {
            int col = n0 + wn + nf * 8 + q * 2;
            __half2 h0 = __float22half2_rn(
                make_float2(acc[mi][nf][0] * d0, acc[mi][nf][1] * d0));
            __half2 h1 = __float22half2_rn(
                make_float2(acc[mi][nf][2] * d1, acc[mi][nf][3] * d1));
            *(__half2*)&g_hh[r0 * DD + col] = h0;
            *(__half2*)&g_hh[r1 * DD + col] = h1;
        }
    }
}

// ---------------------------------------------------------------- spmm ----
// one warp per row; lane owns 8 cols; 8 independent gathers, fp32 accum.
__device__ __forceinline__ void acc_u4(float* a, uint4 v) {
    float2 f0 = __half22float2(*(__half2*)&v.x);
    float2 f1 = __half22float2(*(__half2*)&v.y);
    float2 f2 = __half22float2(*(__half2*)&v.z);
    float2 f3 = __half22float2(*(__half2*)&v.w);
    a[0] += f0.x; a[1] += f0.y; a[2] += f1.x; a[3] += f1.y;
    a[4] += f2.x; a[5] += f2.y; a[6] += f3.x; a[7] += f3.y;
}

__global__ __launch_bounds__(256) void k_spmm(float* __restrict__ out) {
    __shared__ int s_nbr[8][MAXD];
    int lane = threadIdx.x & 31;
    int w    = threadIdx.x >> 5;
    int i    = blockIdx.x * 8 + w;

    int dg = min(g_deg[i], MAXD);
    for (int t = lane; t < dg; t += 32) s_nbr[w][t] = g_nbr[i * MAXD + t];
    __syncwarp();

    const uint4* __restrict__ h4 = (const uint4*)g_hh;
    float acc[8] = {0.f, 0.f, 0.f, 0.f, 0.f, 0.f, 0.f, 0.f};

    int t = 0;
    for (; t + 8 <= dg; t += 8) {
        int4 ja = *(const int4*)&s_nbr[w][t];
        int4 jb = *(const int4*)&s_nbr[w][t + 4];
        uint4 v0 = h4[ja.x * 32 + lane];
        uint4 v1 = h4[ja.y * 32 + lane];
        uint4 v2 = h4[ja.z * 32 + lane];
        uint4 v3 = h4[ja.w * 32 + lane];
        uint4 v4 = h4[jb.x * 32 + lane];
        uint4 v5 = h4[jb.y * 32 + lane];
        uint4 v6 = h4[jb.z * 32 + lane];
        uint4 v7 = h4[jb.w * 32 + lane];
        acc_u4(acc, v0); acc_u4(acc, v1); acc_u4(acc, v2); acc_u4(acc, v3);
        acc_u4(acc, v4); acc_u4(acc, v5); acc_u4(acc, v6); acc_u4(acc, v7);
    }
    for (; t < dg; t++)
        acc_u4(acc, h4[s_nbr[w][t] * 32 + lane]);

    float di = rsqrtf((float)g_deg[i] + 1e-5f);
    float4 r0 = make_float4(fmaxf(acc[0] * di, 0.f), fmaxf(acc[1] * di, 0.f),
                            fmaxf(acc[2] * di, 0.f), fmaxf(acc[3] * di, 0.f));
    float4 r1 = make_float4(fmaxf(acc[4] * di, 0.f), fmaxf(acc[5] * di, 0.f),
                            fmaxf(acc[6] * di, 0.f), fmaxf(acc[7] * di, 0.f));
    *(float4*)&out[i * DD + lane * 8]     = r0;
    *(float4*)&out[i * DD + lane * 8 + 4] = r1;
}

// -------------------------------------------------------------- launch ----
extern "C" void kernel_launch(void* const* d_in, const int* in_sizes, int n_in,
                              void* d_out, int out_size) {
    const float* x    = (const float*)d_in[0];
    const int*   ei32 = (const int*)d_in[1];
    const float* W    = (const float*)d_in[2];
    float*       out  = (float*)d_out;

    int n = in_sizes[0] / DD;   // 8192
    int E = in_sizes[1] / 2;    // 262144

    k_init<<<(n * WPR + 255) / 256, 256>>>(n, ei32);
    k_edges<<<(E + 255) / 256, 256>>>(ei32, E);

    dim3 gg(n / 128, DD / 128);
    k_gemm<<<gg, 256>>>(x, W);

    k_spmm<<<n / 8, 256>>>(out);
}

// round 8
// speedup vs baseline: 1.4699x; 1.2404x over previous
#include <cuda_runtime.h>
#include <cuda_fp16.h>
#include <cuda_bf16.h>
#include <cstdint>

// GCN layer: out = relu(D^-1/2 (I ∪ A) D^-1/2 (x @ W^T))
// N=8192, E=262144 (set semantics -> dedupe), D_IN=D_OUT=256.
//
//   k_init  : bitmap diag (uint4), deg=1, nbr seed; block0 sniffs int64/int32
//   k_edges : atomicOr dedup -> per-row neighbor lists
//   k_gemm  : mma.sync bf16 HMMA, hi/lo split, convert-once 3-pass, 64x128 tile
//   k_spmm  : out[i][:] = relu(dinv[i] * sum_j g_hh[j][:]), fp16 pair-add

#define NN    8192
#define DD    256
#define WPR   (NN / 32)
#define MAXD  128

__device__ uint32_t g_bits[NN * WPR];
__device__ int      g_deg[NN];
__device__ int      g_nbr[NN * MAXD];
__device__ __half   g_hh[NN * DD];        // 4 MB scaled h in fp16
__device__ int      g_is64;

// ---------------------------------------------------------------- init ----
__global__ void k_init(int n, const int* __restrict__ ei32) {
    int idx = blockIdx.x * blockDim.x + threadIdx.x;   // one uint4 (4 words)
    if (idx < n * WPR / 4) {
        int row = idx >> 6;            // 64 uint4 per row
        int w4  = idx & 63;
        uint4 v = make_uint4(0, 0, 0, 0);
        int dw = row >> 5;             // word holding diagonal bit
        if ((dw >> 2) == w4) {
            uint32_t bit = 1u << (row & 31);
            if ((dw & 3) == 0) v.x = bit;
            else if ((dw & 3) == 1) v.y = bit;
            else if ((dw & 3) == 2) v.z = bit;
            else v.w = bit;
        }
        *(uint4*)&g_bits[idx * 4] = v;
    }
    if (idx < n) {
        g_deg[idx] = 1;
        g_nbr[idx * MAXD] = idx;
    }
    if (blockIdx.x == 0) {   // int64 LE => odd int32 words zero
        __shared__ int zc;
        if (threadIdx.x == 0) zc = 0;
        __syncthreads();
        int z = 0;
        for (int t = threadIdx.x; t < 1024; t += 256)
            z += (ei32[2 * t + 1] == 0);
        atomicAdd(&zc, z);
        __syncthreads();
        if (threadIdx.x == 0) g_is64 = (zc >= 1000) ? 1 : 0;
    }
}

// --------------------------------------------------------------- edges ----
__global__ void k_edges(const int* __restrict__ ei32, int E) {
    int e = blockIdx.x * blockDim.x + threadIdx.x;
    if (e < E) {
        int r, c;
        if (g_is64) { r = ei32[2 * e];  c = ei32[2 * (E + e)]; }
        else        { r = ei32[e];      c = ei32[E + e]; }
        r &= (NN - 1);
        c &= (NN - 1);
        uint32_t bit = 1u << (c & 31);
        uint32_t old = atomicOr(&g_bits[r * WPR + (c >> 5)], bit);
        if (!(old & bit)) {
            int p = atomicAdd(&g_deg[r], 1);
            if (p < MAXD) g_nbr[r * MAXD + p] = c;
        }
    }
}

// ---------------------------------------------------------------- gemm ----
// h = x @ W^T, hi/lo bf16 split, convert-once per chunk, 3 MMA passes.
// CTA tile 64(M)x128(N), 8 warps (2x4), warp tile 32x32, K chunks of 64.
#define LDSS 72            // smem row stride in bf16 (144B, conflict-free)
#define OFF_AH 0
#define OFF_AL (64 * LDSS)
#define OFF_BH (128 * LDSS)
#define OFF_BL (256 * LDSS)
#define SM_ELEMS (384 * LDSS)
#define SM_BYTES (SM_ELEMS * 2)

__device__ __forceinline__ uint32_t smem_u32(const void* p) {
    uint32_t a;
    asm("{ .reg .u64 t; cvta.to.shared.u64 t, %1; cvt.u32.u64 %0, t; }"
        : "=r"(a) : "l"(p));
    return a;
}
__device__ __forceinline__ void cvt_both2(float a, float b,
                                          uint32_t& hi, uint32_t& lo) {
    __nv_bfloat162 h = __floats2bfloat162_rn(a, b);
    float2 hf = __bfloat1622float2(h);
    __nv_bfloat162 l = __floats2bfloat162_rn(a - hf.x, b - hf.y);
    hi = *(uint32_t*)&h;
    lo = *(uint32_t*)&l;
}
__device__ __forceinline__ void cvt8_both(float4 f0, float4 f1,
                                          uint4& hi, uint4& lo) {
    cvt_both2(f0.x, f0.y, hi.x, lo.x);
    cvt_both2(f0.z, f0.w, hi.y, lo.y);
    cvt_both2(f1.x, f1.y, hi.z, lo.z);
    cvt_both2(f1.z, f1.w, hi.w, lo.w);
}
#define LDMX4(r0, r1, r2, r3, a)                                             \
    asm volatile("ldmatrix.sync.aligned.m8n8.x4.shared.b16 {%0,%1,%2,%3}, [%4];" \
                 : "=r"(r0), "=r"(r1), "=r"(r2), "=r"(r3) : "r"(a))
#define MMA(c, a0, a1, a2, a3, b0, b1)                                       \
    asm volatile("mma.sync.aligned.m16n8k16.row.col.f32.bf16.bf16.f32 "      \
                 "{%0,%1,%2,%3}, {%4,%5,%6,%7}, {%8,%9}, {%0,%1,%2,%3};"     \
                 : "+f"((c)[0]), "+f"((c)[1]), "+f"((c)[2]), "+f"((c)[3])    \
                 : "r"(a0), "r"(a1), "r"(a2), "r"(a3), "r"(b0), "r"(b1))

__global__ __launch_bounds__(256, 1) void k_gemm(const float* __restrict__ x,
                                                 const float* __restrict__ W) {
    extern __shared__ __nv_bfloat16 sm[];

    int tid  = threadIdx.x;
    int lane = tid & 31;
    int wid  = tid >> 5;
    int wm   = (wid & 1) * 32;            // 2 warps on M
    int wn   = (wid >> 1) * 32;           // 4 warps on N
    int m0   = blockIdx.x * 64;
    int n0   = blockIdx.y * 128;

    uint32_t sb = smem_u32(sm);
    int lrow = lane & 15;
    int lcol = (lane >> 4) * 8;

    float acc[2][4][4];
#pragma unroll
    for (int i = 0; i < 2; i++)
#pragma unroll
        for (int j = 0; j < 4; j++)
#pragma unroll
            for (int q = 0; q < 4; q++) acc[i][j][q] = 0.f;

    int c_row = tid >> 3;                 // 32 rows per 256-thread wave
    int c_grp = tid & 7;

    for (int c = 0; c < 4; c++) {
        int k0 = c * 64;
        __syncthreads();                  // WAR vs previous chunk's reads
        // A: 64 rows -> 2 waves
#pragma unroll
        for (int i = 0; i < 2; i++) {
            int row = c_row + i * 32;
            const float4* s = (const float4*)&x[(m0 + row) * DD + k0 + c_grp * 8];
            uint4 hi, lo;
            cvt8_both(s[0], s[1], hi, lo);
            *(uint4*)&sm[OFF_AH + row * LDSS + c_grp * 8] = hi;
            *(uint4*)&sm[OFF_AL + row * LDSS + c_grp * 8] = lo;
        }
        // B: 128 rows -> 4 waves
#pragma unroll
        for (int i = 0; i < 4; i++) {
            int row = c_row + i * 32;
            const float4* s = (const float4*)&W[(n0 + row) * DD + k0 + c_grp * 8];
            uint4 hi, lo;
            cvt8_both(s[0], s[1], hi, lo);
            *(uint4*)&sm[OFF_BH + row * LDSS + c_grp * 8] = hi;
            *(uint4*)&sm[OFF_BL + row * LDSS + c_grp * 8] = lo;
        }
        __syncthreads();

#pragma unroll
        for (int pass = 0; pass < 3; pass++) {
            uint32_t aoff = (pass == 1) ? OFF_AL : OFF_AH;
            uint32_t boff = (pass == 2) ? OFF_BL : OFF_BH;
#pragma unroll
            for (int kk = 0; kk < 4; kk++) {
                int kc = kk * 16 + lcol;
                uint32_t a[2][4], b[2][4];
#pragma unroll
                for (int mi = 0; mi < 2; mi++) {
                    uint32_t ad = sb + (aoff + (wm + mi * 16 + lrow) * LDSS + kc) * 2;
                    LDMX4(a[mi][0], a[mi][1], a[mi][2], a[mi][3], ad);
                }
#pragma unroll
                for (int nj = 0; nj < 2; nj++) {
                    uint32_t bd = sb + (boff + (wn + nj * 16 + lrow) * LDSS + kc) * 2;
                    LDMX4(b[nj][0], b[nj][1], b[nj][2], b[nj][3], bd);
                }
#pragma unroll
                for (int mi = 0; mi < 2; mi++)
#pragma unroll
                    for (int nf = 0; nf < 4; nf++) {
                        int nj = nf >> 1, hi = nf & 1;
                        MMA(acc[mi][nf], a[mi][0], a[mi][1], a[mi][2], a[mi][3],
                            b[nj][hi], b[nj][2 + hi]);
                    }
            }
        }
    }

    // epilogue: scale rows by rsqrt(deg+eps), store fp16
    int g = lane >> 2;
    int q = lane & 3;
#pragma unroll
    for (int mi = 0; mi < 2; mi++) {
        int r0 = m0 + wm + mi * 16 + g;
        int r1 = r0 + 8;
        float d0 = rsqrtf((float)g_deg[r0] + 1e-5f);
        float d1 = rsqrtf((float)g_deg[r1] + 1e-5f);
#pragma unroll
        for (int nf = 0; nf < 4; nf++) {
            int col = n0 + wn + nf * 8 + q * 2;
            __half2 h0 = __float22half2_rn(
                make_float2(acc[mi][nf][0] * d0, acc[mi][nf][1] * d0));
            __half2 h1 = __float22half2_rn(
                make_float2(acc[mi][nf][2] * d1, acc[mi][nf][3] * d1));
            *(__half2*)&g_hh[r0 * DD + col] = h0;
            *(__half2*)&g_hh[r1 * DD + col] = h1;
        }
    }
}

// ---------------------------------------------------------------- spmm ----
// one warp per row; lane owns 8 cols; fp16 depth-1 pair add, fp32 accum.
__device__ __forceinline__ uint4 hadd4(uint4 a, uint4 b) {
    uint4 r;
    *(__half2*)&r.x = __hadd2(*(__half2*)&a.x, *(__half2*)&b.x);
    *(__half2*)&r.y = __hadd2(*(__half2*)&a.y, *(__half2*)&b.y);
    *(__half2*)&r.z = __hadd2(*(__half2*)&a.z, *(__half2*)&b.z);
    *(__half2*)&r.w = __hadd2(*(__half2*)&a.w, *(__half2*)&b.w);
    return r;
}
__device__ __forceinline__ void acc_u4(float* a, uint4 v) {
    float2 f0 = __half22float2(*(__half2*)&v.x);
    float2 f1 = __half22float2(*(__half2*)&v.y);
    float2 f2 = __half22float2(*(__half2*)&v.z);
    float2 f3 = __half22float2(*(__half2*)&v.w);
    a[0] += f0.x; a[1] += f0.y; a[2] += f1.x; a[3] += f1.y;
    a[4] += f2.x; a[5] += f2.y; a[6] += f3.x; a[7] += f3.y;
}

__global__ __launch_bounds__(256) void k_spmm(float* __restrict__ out) {
    __shared__ int s_nbr[8][MAXD];
    int lane = threadIdx.x & 31;
    int w    = threadIdx.x >> 5;
    int i    = blockIdx.x * 8 + w;

    int dg = min(g_deg[i], MAXD);
    for (int t = lane; t < dg; t += 32) s_nbr[w][t] = g_nbr[i * MAXD + t];
    __syncwarp();

    const uint4* __restrict__ h4 = (const uint4*)g_hh;
    float acc[8] = {0.f, 0.f, 0.f, 0.f, 0.f, 0.f, 0.f, 0.f};

    int t = 0;
    for (; t + 8 <= dg; t += 8) {
        int4 ja = *(const int4*)&s_nbr[w][t];
        int4 jb = *(const int4*)&s_nbr[w][t + 4];
        uint4 v0 = h4[ja.x * 32 + lane];
        uint4 v1 = h4[ja.y * 32 + lane];
        uint4 v2 = h4[ja.z * 32 + lane];
        uint4 v3 = h4[ja.w * 32 + lane];
        uint4 v4 = h4[jb.x * 32 + lane];
        uint4 v5 = h4[jb.y * 32 + lane];
        uint4 v6 = h4[jb.z * 32 + lane];
        uint4 v7 = h4[jb.w * 32 + lane];
        acc_u4(acc, hadd4(v0, v1));
        acc_u4(acc, hadd4(v2, v3));
        acc_u4(acc, hadd4(v4, v5));
        acc_u4(acc, hadd4(v6, v7));
    }
    for (; t + 2 <= dg; t += 2) {
        uint4 va = h4[s_nbr[w][t] * 32 + lane];
        uint4 vb = h4[s_nbr[w][t + 1] * 32 + lane];
        acc_u4(acc, hadd4(va, vb));
    }
    for (; t < dg; t++)
        acc_u4(acc, h4[s_nbr[w][t] * 32 + lane]);

    float di = rsqrtf((float)g_deg[i] + 1e-5f);
    float4 r0 = make_float4(fmaxf(acc[0] * di, 0.f), fmaxf(acc[1] * di, 0.f),
                            fmaxf(acc[2] * di, 0.f), fmaxf(acc[3] * di, 0.f));
    float4 r1 = make_float4(fmaxf(acc[4] * di, 0.f), fmaxf(acc[5] * di, 0.f),
                            fmaxf(acc[6] * di, 0.f), fmaxf(acc[7] * di, 0.f));
    *(float4*)&out[i * DD + lane * 8]     = r0;
    *(float4*)&out[i * DD + lane * 8 + 4] = r1;
}

// -------------------------------------------------------------- launch ----
extern "C" void kernel_launch(void* const* d_in, const int* in_sizes, int n_in,
                              void* d_out, int out_size) {
    const float* x    = (const float*)d_in[0];
    const int*   ei32 = (const int*)d_in[1];
    const float* W    = (const float*)d_in[2];
    float*       out  = (float*)d_out;

    int n = in_sizes[0] / DD;   // 8192
    int E = in_sizes[1] / 2;    // 262144

    k_init<<<(n * WPR / 4 + 255) / 256, 256>>>(n, ei32);
    k_edges<<<(E + 255) / 256, 256>>>(ei32, E);

    cudaFuncSetAttribute(k_gemm, cudaFuncAttributeMaxDynamicSharedMemorySize,
                         SM_BYTES);
    dim3 gg(n / 64, DD / 128);
    k_gemm<<<gg, 256, SM_BYTES>>>(x, W);

    k_spmm<<<n / 8, 256>>>(out);
}

// round 9
// speedup vs baseline: 1.6412x; 1.1166x over previous
#include <cuda_runtime.h>
#include <cuda_fp16.h>
#include <cuda_bf16.h>
#include <cstdint>

// GCN layer: out = relu(D^-1/2 (I ∪ A) D^-1/2 (x @ W^T))
// N=8192, E=262144 (set semantics -> dedupe), D_IN=D_OUT=256.
//
// Two independent chains, overlapped via graph fork/join:
//   s1: k_init -> k_edges            (bitmap dedup, neighbor lists, deg)
//   s2: k_gemm                        (h = x@W^T, bf16 hi/lo HMMA, UNscaled fp16)
//   join -> k_spmm : out[i] = relu(dinv[i] * sum_j dinv[j]*h[j])

#define NN    8192
#define DD    256
#define WPR   (NN / 32)
#define MAXD  128

__device__ uint32_t g_bits[NN * WPR];
__device__ int      g_deg[NN];
__device__ int      g_nbr[NN * MAXD];
__device__ __half   g_hh[NN * DD];        // 4 MB h (unscaled) in fp16
__device__ int      g_is64;

// ---------------------------------------------------------------- init ----
__global__ void k_init(int n, const int* __restrict__ ei32) {
    int idx = blockIdx.x * blockDim.x + threadIdx.x;   // one uint4 (4 words)
    if (idx < n * WPR / 4) {
        int row = idx >> 6;            // 64 uint4 per row
        int w4  = idx & 63;
        uint4 v = make_uint4(0, 0, 0, 0);
        int dw = row >> 5;             // word holding diagonal bit
        if ((dw >> 2) == w4) {
            uint32_t bit = 1u << (row & 31);
            if ((dw & 3) == 0) v.x = bit;
            else if ((dw & 3) == 1) v.y = bit;
            else if ((dw & 3) == 2) v.z = bit;
            else v.w = bit;
        }
        *(uint4*)&g_bits[idx * 4] = v;
    }
    if (idx < n) {
        g_deg[idx] = 1;
        g_nbr[idx * MAXD] = idx;
    }
    if (blockIdx.x == 0) {   // int64 LE => odd int32 words zero
        __shared__ int zc;
        if (threadIdx.x == 0) zc = 0;
        __syncthreads();
        int z = 0;
        for (int t = threadIdx.x; t < 1024; t += 256)
            z += (ei32[2 * t + 1] == 0);
        atomicAdd(&zc, z);
        __syncthreads();
        if (threadIdx.x == 0) g_is64 = (zc >= 1000) ? 1 : 0;
    }
}

// --------------------------------------------------------------- edges ----
__global__ void k_edges(const int* __restrict__ ei32, int E) {
    int e = blockIdx.x * blockDim.x + threadIdx.x;
    if (e < E) {
        int r, c;
        if (g_is64) { r = ei32[2 * e];  c = ei32[2 * (E + e)]; }
        else        { r = ei32[e];      c = ei32[E + e]; }
        r &= (NN - 1);
        c &= (NN - 1);
        uint32_t bit = 1u << (c & 31);
        uint32_t old = atomicOr(&g_bits[r * WPR + (c >> 5)], bit);
        if (!(old & bit)) {
            int p = atomicAdd(&g_deg[r], 1);
            if (p < MAXD) g_nbr[r * MAXD + p] = c;
        }
    }
}

// ---------------------------------------------------------------- gemm ----
// h = x @ W^T, hi/lo bf16 split, convert-once per chunk, 3 MMA passes.
// CTA tile 64(M)x128(N), 8 warps (2x4), warp tile 32x32, K chunks of 64.
// NO dependency on g_deg: stores unscaled fp16.
#define LDSS 72            // smem row stride in bf16 (144B, conflict-free)
#define OFF_AH 0
#define OFF_AL (64 * LDSS)
#define OFF_BH (128 * LDSS)
#define OFF_BL (256 * LDSS)
#define SM_ELEMS (384 * LDSS)
#define SM_BYTES (SM_ELEMS * 2)

__device__ __forceinline__ uint32_t smem_u32(const void* p) {
    uint32_t a;
    asm("{ .reg .u64 t; cvta.to.shared.u64 t, %1; cvt.u32.u64 %0, t; }"
        : "=r"(a) : "l"(p));
    return a;
}
__device__ __forceinline__ void cvt_both2(float a, float b,
                                          uint32_t& hi, uint32_t& lo) {
    __nv_bfloat162 h = __floats2bfloat162_rn(a, b);
    float2 hf = __bfloat1622float2(h);
    __nv_bfloat162 l = __floats2bfloat162_rn(a - hf.x, b - hf.y);
    hi = *(uint32_t*)&h;
    lo = *(uint32_t*)&l;
}
__device__ __forceinline__ void cvt8_both(float4 f0, float4 f1,
                                          uint4& hi, uint4& lo) {
    cvt_both2(f0.x, f0.y, hi.x, lo.x);
    cvt_both2(f0.z, f0.w, hi.y, lo.y);
    cvt_both2(f1.x, f1.y, hi.z, lo.z);
    cvt_both2(f1.z, f1.w, hi.w, lo.w);
}
#define LDMX4(r0, r1, r2, r3, a)                                             \
    asm volatile("ldmatrix.sync.aligned.m8n8.x4.shared.b16 {%0,%1,%2,%3}, [%4];" \
                 : "=r"(r0), "=r"(r1), "=r"(r2), "=r"(r3) : "r"(a))
#define MMA(c, a0, a1, a2, a3, b0, b1)                                       \
    asm volatile("mma.sync.aligned.m16n8k16.row.col.f32.bf16.bf16.f32 "      \
                 "{%0,%1,%2,%3}, {%4,%5,%6,%7}, {%8,%9}, {%0,%1,%2,%3};"     \
                 : "+f"((c)[0]), "+f"((c)[1]), "+f"((c)[2]), "+f"((c)[3])    \
                 : "r"(a0), "r"(a1), "r"(a2), "r"(a3), "r"(b0), "r"(b1))

__global__ __launch_bounds__(256, 1) void k_gemm(const float* __restrict__ x,
                                                 const float* __restrict__ W) {
    extern __shared__ __nv_bfloat16 sm[];

    int tid  = threadIdx.x;
    int lane = tid & 31;
    int wid  = tid >> 5;
    int wm   = (wid & 1) * 32;            // 2 warps on M
    int wn   = (wid >> 1) * 32;           // 4 warps on N
    int m0   = blockIdx.x * 64;
    int n0   = blockIdx.y * 128;

    uint32_t sb = smem_u32(sm);
    int lrow = lane & 15;
    int lcol = (lane >> 4) * 8;

    float acc[2][4][4];
#pragma unroll
    for (int i = 0; i < 2; i++)
#pragma unroll
        for (int j = 0; j < 4; j++)
#pragma unroll
            for (int q = 0; q < 4; q++) acc[i][j][q] = 0.f;

    int c_row = tid >> 3;                 // 32 rows per 256-thread wave
    int c_grp = tid & 7;

    for (int c = 0; c < 4; c++) {
        int k0 = c * 64;
        __syncthreads();                  // WAR vs previous chunk's reads
#pragma unroll
        for (int i = 0; i < 2; i++) {     // A: 64 rows
            int row = c_row + i * 32;
            const float4* s = (const float4*)&x[(m0 + row) * DD + k0 + c_grp * 8];
            uint4 hi, lo;
            cvt8_both(s[0], s[1], hi, lo);
            *(uint4*)&sm[OFF_AH + row * LDSS + c_grp * 8] = hi;
            *(uint4*)&sm[OFF_AL + row * LDSS + c_grp * 8] = lo;
        }
#pragma unroll
        for (int i = 0; i < 4; i++) {     // B: 128 rows
            int row = c_row + i * 32;
            const float4* s = (const float4*)&W[(n0 + row) * DD + k0 + c_grp * 8];
            uint4 hi, lo;
            cvt8_both(s[0], s[1], hi, lo);
            *(uint4*)&sm[OFF_BH + row * LDSS + c_grp * 8] = hi;
            *(uint4*)&sm[OFF_BL + row * LDSS + c_grp * 8] = lo;
        }
        __syncthreads();

#pragma unroll
        for (int pass = 0; pass < 3; pass++) {
            uint32_t aoff = (pass == 1) ? OFF_AL : OFF_AH;
            uint32_t boff = (pass == 2) ? OFF_BL : OFF_BH;
#pragma unroll
            for (int kk = 0; kk < 4; kk++) {
                int kc = kk * 16 + lcol;
                uint32_t a[2][4], b[2][4];
#pragma unroll
                for (int mi = 0; mi < 2; mi++) {
                    uint32_t ad = sb + (aoff + (wm + mi * 16 + lrow) * LDSS + kc) * 2;
                    LDMX4(a[mi][0], a[mi][1], a[mi][2], a[mi][3], ad);
                }
#pragma unroll
                for (int nj = 0; nj < 2; nj++) {
                    uint32_t bd = sb + (boff + (wn + nj * 16 + lrow) * LDSS + kc) * 2;
                    LDMX4(b[nj][0], b[nj][1], b[nj][2], b[nj][3], bd);
                }
#pragma unroll
                for (int mi = 0; mi < 2; mi++)
#pragma unroll
                    for (int nf = 0; nf < 4; nf++) {
                        int nj = nf >> 1, hi = nf & 1;
                        MMA(acc[mi][nf], a[mi][0], a[mi][1], a[mi][2], a[mi][3],
                            b[nj][hi], b[nj][2 + hi]);
                    }
            }
        }
    }

    // epilogue: store UNscaled fp16
    int g = lane >> 2;
    int q = lane & 3;
#pragma unroll
    for (int mi = 0; mi < 2; mi++) {
        int r0 = m0 + wm + mi * 16 + g;
        int r1 = r0 + 8;
#pragma unroll
        for (int nf = 0; nf < 4; nf++) {
            int col = n0 + wn + nf * 8 + q * 2;
            __half2 h0 = __float22half2_rn(
                make_float2(acc[mi][nf][0], acc[mi][nf][1]));
            __half2 h1 = __float22half2_rn(
                make_float2(acc[mi][nf][2], acc[mi][nf][3]));
            *(__half2*)&g_hh[r0 * DD + col] = h0;
            *(__half2*)&g_hh[r1 * DD + col] = h1;
        }
    }
}

// ---------------------------------------------------------------- spmm ----
// one warp per row; lane owns 8 cols; per-neighbor dinv[j] scale via FFMA.
__device__ __forceinline__ void accs(float* a, uint4 v, float d) {
    float2 f0 = __half22float2(*(__half2*)&v.x);
    float2 f1 = __half22float2(*(__half2*)&v.y);
    float2 f2 = __half22float2(*(__half2*)&v.z);
    float2 f3 = __half22float2(*(__half2*)&v.w);
    a[0] = fmaf(f0.x, d, a[0]); a[1] = fmaf(f0.y, d, a[1]);
    a[2] = fmaf(f1.x, d, a[2]); a[3] = fmaf(f1.y, d, a[3]);
    a[4] = fmaf(f2.x, d, a[4]); a[5] = fmaf(f2.y, d, a[5]);
    a[6] = fmaf(f3.x, d, a[6]); a[7] = fmaf(f3.y, d, a[7]);
}

__global__ __launch_bounds__(256) void k_spmm(float* __restrict__ out) {
    __shared__ int   s_nbr[8][MAXD];
    __shared__ float s_dj[8][MAXD];
    int lane = threadIdx.x & 31;
    int w    = threadIdx.x >> 5;
    int i    = blockIdx.x * 8 + w;

    int dg = min(g_deg[i], MAXD);
    for (int t = lane; t < dg; t += 32) {
        int j = g_nbr[i * MAXD + t];
        s_nbr[w][t] = j;
        s_dj[w][t]  = rsqrtf((float)g_deg[j] + 1e-5f);
    }
    __syncwarp();

    const uint4* __restrict__ h4 = (const uint4*)g_hh;
    float acc[8] = {0.f, 0.f, 0.f, 0.f, 0.f, 0.f, 0.f, 0.f};

    int t = 0;
    for (; t + 8 <= dg; t += 8) {
        int4   ja = *(const int4*)&s_nbr[w][t];
        int4   jb = *(const int4*)&s_nbr[w][t + 4];
        float4 da = *(const float4*)&s_dj[w][t];
        float4 db = *(const float4*)&s_dj[w][t + 4];
        uint4 v0 = h4[ja.x * 32 + lane];
        uint4 v1 = h4[ja.y * 32 + lane];
        uint4 v2 = h4[ja.z * 32 + lane];
        uint4 v3 = h4[ja.w * 32 + lane];
        uint4 v4 = h4[jb.x * 32 + lane];
        uint4 v5 = h4[jb.y * 32 + lane];
        uint4 v6 = h4[jb.z * 32 + lane];
        uint4 v7 = h4[jb.w * 32 + lane];
        accs(acc, v0, da.x); accs(acc, v1, da.y);
        accs(acc, v2, da.z); accs(acc, v3, da.w);
        accs(acc, v4, db.x); accs(acc, v5, db.y);
        accs(acc, v6, db.z); accs(acc, v7, db.w);
    }
    for (; t < dg; t++)
        accs(acc, h4[s_nbr[w][t] * 32 + lane], s_dj[w][t]);

    float di = rsqrtf((float)g_deg[i] + 1e-5f);
    float4 r0 = make_float4(fmaxf(acc[0] * di, 0.f), fmaxf(acc[1] * di, 0.f),
                            fmaxf(acc[2] * di, 0.f), fmaxf(acc[3] * di, 0.f));
    float4 r1 = make_float4(fmaxf(acc[4] * di, 0.f), fmaxf(acc[5] * di, 0.f),
                            fmaxf(acc[6] * di, 0.f), fmaxf(acc[7] * di, 0.f));
    *(float4*)&out[i * DD + lane * 8]     = r0;
    *(float4*)&out[i * DD + lane * 8 + 4] = r1;
}

// -------------------------------------------------------------- launch ----
// Fork/join: s1 runs graph build, s2 runs GEMM (independent), join -> spmm.
// Streams/events created once on first (uncaptured correctness) call;
// every call performs identical GPU work.
static cudaStream_t s_g1, s_g2;
static cudaEvent_t  s_ev0, s_ev1, s_ev2;
static bool s_ready = false;

extern "C" void kernel_launch(void* const* d_in, const int* in_sizes, int n_in,
                              void* d_out, int out_size) {
    const float* x    = (const float*)d_in[0];
    const int*   ei32 = (const int*)d_in[1];
    const float* W    = (const float*)d_in[2];
    float*       out  = (float*)d_out;

    int n = in_sizes[0] / DD;   // 8192
    int E = in_sizes[1] / 2;    // 262144

    if (!s_ready) {
        cudaStreamCreateWithFlags(&s_g1, cudaStreamNonBlocking);
        cudaStreamCreateWithFlags(&s_g2, cudaStreamNonBlocking);
        cudaEventCreateWithFlags(&s_ev0, cudaEventDisableTiming);
        cudaEventCreateWithFlags(&s_ev1, cudaEventDisableTiming);
        cudaEventCreateWithFlags(&s_ev2, cudaEventDisableTiming);
        cudaFuncSetAttribute(k_gemm, cudaFuncAttributeMaxDynamicSharedMemorySize,
                             SM_BYTES);
        s_ready = true;
    }

    // fork from the (captured) legacy stream
    cudaEventRecord(s_ev0, 0);
    cudaStreamWaitEvent(s_g1, s_ev0, 0);
    cudaStreamWaitEvent(s_g2, s_ev0, 0);

    // branch 1: graph build
    k_init <<<(n * WPR / 4 + 255) / 256, 256, 0, s_g1>>>(n, ei32);
    k_edges<<<(E + 255) / 256, 256, 0, s_g1>>>(ei32, E);

    // branch 2: dense GEMM (no dependency on branch 1)
    dim3 gg(n / 64, DD / 128);
    k_gemm<<<gg, 256, SM_BYTES, s_g2>>>(x, W);

    // join
    cudaEventRecord(s_ev1, s_g1);
    cudaEventRecord(s_ev2, s_g2);
    cudaStreamWaitEvent(0, s_ev1, 0);
    cudaStreamWaitEvent(0, s_ev2, 0);

    k_spmm<<<n / 8, 256>>>(out);
}